// round 16
// baseline (speedup 1.0000x reference)
#include <cuda_runtime.h>
#include <cuda_bf16.h>
#include <cuda_fp16.h>
#include <math.h>

#define B_ 8
#define T_ 2048
#define H_ 64
#define M_ 32
#define S_ 20
#define E_ 3
#define IN_ 32
#define EPS_ 1e-8f
#define THR_ 30.0f  // bf16 MMA err ~<3 + half Tmx err ~<1 << 30; dropped mass ~e^-26

#define QKV_BLOCKS_ (E_*B_*T_/64)   // 768
#define MEM_BLOCKS_ (B_*T_/8)       // 2048

// Scratch (allocation-free rule: __device__ globals)
__device__ float g_mem[B_*T_*M_];
__device__ float g_Q[E_*B_*T_*M_];
__device__ float g_K[E_*B_*T_*M_];
__device__ float g_V[E_*B_*T_*M_];
__device__ __nv_bfloat16 g_Qb[E_*B_*T_*M_];
__device__ __nv_bfloat16 g_Kb[E_*B_*T_*M_];

__device__ __forceinline__ float warpSum(float v){
  #pragma unroll
  for (int o=16;o>0;o>>=1) v += __shfl_xor_sync(0xffffffffu, v, o);
  return v;
}
__device__ __forceinline__ float warpMax(float v){
  #pragma unroll
  for (int o=16;o>0;o>>=1) v = fmaxf(v, __shfl_xor_sync(0xffffffffu, v, o));
  return v;
}

__device__ __forceinline__ void mma16816(float* c, const unsigned* a,
                                         unsigned b0, unsigned b1){
  asm volatile(
    "mma.sync.aligned.m16n8k16.row.col.f32.bf16.bf16.f32 "
    "{%0,%1,%2,%3}, {%4,%5,%6,%7}, {%8,%9}, {%0,%1,%2,%3};\n"
    : "+f"(c[0]), "+f"(c[1]), "+f"(c[2]), "+f"(c[3])
    : "r"(a[0]), "r"(a[1]), "r"(a[2]), "r"(a[3]), "r"(b0), "r"(b1));
}

// ---------------------------------------------------------------------------
// Kernel 1 (combined prep): blocks [0, 768)     -> QKV projections
//                           blocks [768, 2816)  -> memory soft-read
// mem blocks backfill SMs alongside the qkv blocks.
// ---------------------------------------------------------------------------
__global__ __launch_bounds__(256) void prep_kernel(
    const float* __restrict__ x,      const float* __restrict__ hidden,
    const float* __restrict__ memory, const float* __restrict__ Wq,
    const float* __restrict__ Wk,     const float* __restrict__ Wv,
    const float* __restrict__ iq)
{
  __shared__ float sA[H_*M_], sB[H_*M_], sC[H_*M_];  // qkv: Wq/Wk/Wv; mem: IQ+MEMT
  int tid = threadIdx.x, warp = tid >> 5, lane = tid & 31;
  int bx = blockIdx.x;

  if (bx < QKV_BLOCKS_){
    // ---- QKV: e = bx % 3, 64 rows starting at (bx/3)*64 (covers all B_*T_) --
    int e = bx % E_;
    for (int i = tid; i < H_*M_; i += 256){
      sA[i] = Wq[e*H_*M_ + i];
      sB[i] = Wk[e*H_*M_ + i];
      sC[i] = Wv[e*H_*M_ + i];
    }
    __syncthreads();
    int rowBase = (bx/E_)*64 + warp*8;
    #pragma unroll
    for (int rr = 0; rr < 8; rr++){
      int row = rowBase + rr;
      long gr = (long)e*B_*T_ + row;
      float h0 = hidden[gr*H_ + lane];
      float h1 = hidden[gr*H_ + 32 + lane];
      float q = 0.f, k = 0.f, v = 0.f;
      #pragma unroll
      for (int h = 0; h < 32; h++){
        float hv = __shfl_sync(0xffffffffu, h0, h);
        q += hv*sA[h*M_+lane]; k += hv*sB[h*M_+lane]; v += hv*sC[h*M_+lane];
      }
      #pragma unroll
      for (int h = 0; h < 32; h++){
        float hv = __shfl_sync(0xffffffffu, h1, h);
        q += hv*sA[(h+32)*M_+lane]; k += hv*sB[(h+32)*M_+lane]; v += hv*sC[(h+32)*M_+lane];
      }
      g_Q[gr*M_+lane] = q; g_K[gr*M_+lane] = k; g_V[gr*M_+lane] = v;
      g_Qb[gr*M_+lane] = __float2bfloat16(q);
      g_Kb[gr*M_+lane] = __float2bfloat16(k);
    }
  } else {
    // ---- memory soft-read: 8 (b,t) rows per block, 1 per warp ----
    float* IQs  = sA;                  // [IN_*M_] = 1024 floats
    float* MEMT = sB;                  // [33*33] = 1089 floats (fits 2048)
    for (int i = tid; i < IN_*M_; i += 256) IQs[i] = iq[i];
    for (int i = tid; i < 33*33;  i += 256){
      int s = i / 33, m = i % 33;
      MEMT[i] = (s < S_ && m < M_) ? memory[s*M_ + m] : 0.f;
    }
    __syncthreads();
    int bt = (bx - QKV_BLOCKS_)*8 + warp;

    float xv = x[bt*IN_ + lane];
    float q = 0.f;
    #pragma unroll
    for (int i = 0; i < IN_; i++)
      q += __shfl_sync(0xffffffffu, xv, i) * IQs[i*M_ + lane];

    float sc = 0.f;
    #pragma unroll
    for (int m = 0; m < M_; m++)
      sc = fmaf(__shfl_sync(0xffffffffu, q, m), MEMT[lane*33 + m], sc);
    float mx = warpMax(lane < S_ ? sc : -INFINITY);
    float p  = (lane < S_) ? __expf(sc - mx) : 0.f;
    float sum = warpSum(p);

    float mval = 0.f;
    #pragma unroll
    for (int s = 0; s < S_; s++)
      mval = fmaf(__shfl_sync(0xffffffffu, p, s), MEMT[s*33 + lane], mval);
    g_mem[bt*M_ + lane] = mval / sum;
  }
}

// ---------------------------------------------------------------------------
// Kernel 2 (fused attention): pass1 (bf16 HMMA tile maxes, Tmx in smem) ->
// survivor lists -> pass2 (R12 visit engine) -> cosine epilogue.
// smem regions (bytes):
//  X [0, 33792): pass1 KstRaw[0,10240) + Tmx half[10240,26624);
//                pass2 Kbuf f32[4][32][33] [0,16896), Vbuf [16896,33792)
//                (aliased; list build completes before first staging barrier)
//  P [36864, 58624): accS[128*32] | lS[128] | Rm[128] | cnt[64] | list[64*64]
// ---------------------------------------------------------------------------
#define AT_SMEM_ 59776

__global__ __launch_bounds__(256, 3) void attn_fused(float* __restrict__ out)
{
  extern __shared__ char sm[];
  // region X
  char*   KstRaw = sm;                          // pass1: 128 keys x 80B
  __half* Tmx    = (__half*)(sm + 10240);       // pass1/listing: [128][64]
  float*  Kbuf   = (float*)sm;                  // pass2: [4][32][33]
  float*  Vbuf   = (float*)(sm + 16896);        // pass2: [4][32][33]
  // region P (persistent)
  float* accS = (float*)(sm + 36864);           // [128][32]
  float* lS   = accS + 4096;                    // [128]
  float* Rm   = lS + 128;                       // [128]
  int*   cnt  = (int*)(Rm + 128);               // [64]
  unsigned char* list = (unsigned char*)(cnt + 64);  // [64][64]

  int tid = threadIdx.x, w = tid >> 5, lane = tid & 31;
  int gid = lane >> 2, tig = lane & 3;
  int eb = blockIdx.y, e = eb / B_, b = eb % B_;
  size_t ebT = (size_t)eb * T_;
  int qbase = blockIdx.x * 128;

  // persistent-region init (disjoint from pass1 smem)
  for (int i = tid; i < 128*32; i += 256) accS[i] = 0.f;
  if (tid < 128) lS[tid] = 0.f;
  if (tid < 64) cnt[tid] = 0;

  // ======================= pass 1: bf16 HMMA tile maxes ====================
  {
    int row_lo = qbase + w*16 + gid, row_hi = row_lo + 8;
    unsigned a[8];
    const __nv_bfloat16* q0 = g_Qb + (ebT + row_lo)*M_;
    const __nv_bfloat16* q1 = g_Qb + (ebT + row_hi)*M_;
    a[0]=*(const unsigned*)(q0+2*tig);    a[1]=*(const unsigned*)(q1+2*tig);
    a[2]=*(const unsigned*)(q0+2*tig+8);  a[3]=*(const unsigned*)(q1+2*tig+8);
    a[4]=*(const unsigned*)(q0+2*tig+16); a[5]=*(const unsigned*)(q1+2*tig+16);
    a[6]=*(const unsigned*)(q0+2*tig+24); a[7]=*(const unsigned*)(q1+2*tig+24);

    float mlo = -INFINITY, mhi = -INFINITY;
    const unsigned* Kbg = (const unsigned*)(g_Kb + ebT*M_);
    unsigned pf[8];
    #pragma unroll
    for (int i = 0; i < 8; i++) pf[i] = Kbg[tid + i*256];

    for (int c = 0; c < 16; c++){
      __syncthreads();
      #pragma unroll
      for (int i = 0; i < 8; i++){
        int lidx = tid + i*256;
        *(unsigned*)(KstRaw + (lidx >> 4)*80 + (lidx & 15)*4) = pf[i];
      }
      __syncthreads();
      if (c < 15){
        #pragma unroll
        for (int i = 0; i < 8; i++) pf[i] = Kbg[(c+1)*2048 + tid + i*256];
      }
      #pragma unroll
      for (int t = 0; t < 4; t++){
        int kt = c*4 + t;
        float tlo = -INFINITY, thi = -INFINITY;
        #pragma unroll
        for (int nb = 0; nb < 4; nb++){
          const char* bp = KstRaw + (t*32 + nb*8 + gid)*80 + tig*4;
          unsigned b0 = *(const unsigned*)(bp);
          unsigned b1 = *(const unsigned*)(bp + 16);
          unsigned b2 = *(const unsigned*)(bp + 32);
          unsigned b3 = *(const unsigned*)(bp + 48);
          float cc[4] = {0.f, 0.f, 0.f, 0.f};
          mma16816(cc, a,   b0, b1);
          mma16816(cc, a+4, b2, b3);
          tlo = fmaxf(tlo, fmaxf(cc[0], cc[1]));
          thi = fmaxf(thi, fmaxf(cc[2], cc[3]));
        }
        tlo = fmaxf(tlo, __shfl_xor_sync(0xffffffffu, tlo, 1));
        tlo = fmaxf(tlo, __shfl_xor_sync(0xffffffffu, tlo, 2));
        thi = fmaxf(thi, __shfl_xor_sync(0xffffffffu, thi, 1));
        thi = fmaxf(thi, __shfl_xor_sync(0xffffffffu, thi, 2));
        if (tig == 0){
          Tmx[(w*16 + gid)*64 + kt]     = __float2half_rn(tlo);
          Tmx[(w*16 + gid + 8)*64 + kt] = __float2half_rn(thi);
        }
        mlo = fmaxf(mlo, tlo); mhi = fmaxf(mhi, thi);
      }
    }
    if (tig == 0){ Rm[w*16 + gid] = mlo; Rm[w*16 + gid + 8] = mhi; }
  }
  __syncthreads();     // Tmx + Rm complete

  // =================== survivor lists (Tmx, Rm from smem) ==================
  #pragma unroll
  for (int j = 0; j < 32; j++){
    int p  = tid + j*256;               // p = row*64 + kt
    int row = p >> 6, kt = p & 63;
    if (__half2float(Tmx[p]) >= Rm[row] - THR_){
      int slot = atomicAdd(&cnt[kt], 1);
      if (slot < 64) list[kt*64 + slot] = (unsigned char)row;
    }
  }

  // ====================== pass 2: R12 visit engine =========================
  const float* Kg = g_K + ebT*M_;
  const float* Vg = g_V + ebT*M_;
  const float* Qg = g_Q + (ebT + qbase)*M_;

  float4 pk4[4], pv4[4];
  #pragma unroll
  for (int j = 0; j < 4; j++){
    pk4[j] = __ldg((const float4*)(Kg) + tid + j*256);
    pv4[j] = __ldg((const float4*)(Vg) + tid + j*256);
  }

  for (int g = 0; g < 16; g++){
    __syncthreads();                       // Kbuf/Vbuf free; fences lists/Tmx
    #pragma unroll
    for (int j = 0; j < 4; j++){
      int f = tid + j*256;                 // float4 idx: key = f>>3, m0 = (f&7)*4
      int key = f >> 3, m0 = (f & 7)*4;
      float* kd = Kbuf + (key >> 5)*1056 + (key & 31)*33 + m0;
      float* vd = Vbuf + (key >> 5)*1056 + (key & 31)*33 + m0;
      kd[0]=pk4[j].x; kd[1]=pk4[j].y; kd[2]=pk4[j].z; kd[3]=pk4[j].w;
      vd[0]=pv4[j].x; vd[1]=pv4[j].y; vd[2]=pv4[j].z; vd[3]=pv4[j].w;
    }
    __syncthreads();                       // tiles ready
    if (g < 15){
      #pragma unroll
      for (int j = 0; j < 4; j++){
        pk4[j] = __ldg((const float4*)(Kg) + (g+1)*1024 + tid + j*256);
        pv4[j] = __ldg((const float4*)(Vg) + (g+1)*1024 + tid + j*256);
      }
    }

    #pragma unroll 1
    for (int t = 0; t < 4; t++){           // ascending tile order (determinism)
      int kt = g*4 + t;
      int n = min(cnt[kt], 64);
      const float* Kt = Kbuf + t*1056;
      const float* Vt = Vbuf + t*1056;
      #pragma unroll 1
      for (int v = 0; v < n; v++){
        int row = list[kt*64 + v];
        if ((row & 7) != w) continue;      // warp owns rows ≡ w (mod 8)
        float q = Qg[(size_t)row*32 + lane];   // lane = m
        float s0 = 0.f, s1 = 0.f, s2 = 0.f, s3 = 0.f;
        #pragma unroll
        for (int m = 0; m < 8; m++){
          s0 = fmaf(__shfl_sync(0xffffffffu, q, m),      Kt[lane*33 + m],      s0);
          s1 = fmaf(__shfl_sync(0xffffffffu, q, m + 8),  Kt[lane*33 + m + 8],  s1);
          s2 = fmaf(__shfl_sync(0xffffffffu, q, m + 16), Kt[lane*33 + m + 16], s2);
          s3 = fmaf(__shfl_sync(0xffffffffu, q, m + 24), Kt[lane*33 + m + 24], s3);
        }
        float s = (s0 + s1) + (s2 + s3);
        float p = __expf(s - Rm[row]);     // shift cancels in acc/l exactly
        float sum = warpSum(p);
        float a0 = accS[row*32 + lane], a1 = 0.f;
        #pragma unroll
        for (int k = 0; k < 16; k++){
          a0 = fmaf(__shfl_sync(0xffffffffu, p, k),      Vt[k*33 + lane],        a0);
          a1 = fmaf(__shfl_sync(0xffffffffu, p, k + 16), Vt[(k + 16)*33 + lane], a1);
        }
        accS[row*32 + lane] = a0 + a1;
        if (lane == 0) lS[row] += sum;
      }
    }
  }
  __syncthreads();

  // ===================== epilogue: cosine vs memories ======================
  for (int r = 0; r < 16; r++){
    int row = w*16 + r, t = qbase + row;
    float o  = accS[row*32 + lane] / lS[row];
    float mv = g_mem[((size_t)b*T_ + t)*M_ + lane];
    float d  = warpSum(o*mv);
    float n1 = warpSum(o*o);
    float n2 = warpSum(mv*mv);
    if (lane == 0)
      out[((size_t)b*T_ + t)*E_ + e] =
          d / (fmaxf(sqrtf(n1), EPS_) * fmaxf(sqrtf(n2), EPS_));
  }
}

// ---------------------------------------------------------------------------
extern "C" void kernel_launch(void* const* d_in, const int* in_sizes, int n_in,
                              void* d_out, int out_size)
{
  const float* x      = (const float*)d_in[0];
  const float* hidden = (const float*)d_in[1];
  const float* memory = (const float*)d_in[2];
  const float* Wq     = (const float*)d_in[3];
  const float* Wk     = (const float*)d_in[4];
  const float* Wv     = (const float*)d_in[5];
  const float* iq     = (const float*)d_in[6];
  float* out = (float*)d_out;

  cudaFuncSetAttribute(attn_fused, cudaFuncAttributeMaxDynamicSharedMemorySize,
                       AT_SMEM_);

  prep_kernel<<<QKV_BLOCKS_ + MEM_BLOCKS_, 256>>>(x, hidden, memory,
                                                  Wq, Wk, Wv, iq);
  attn_fused<<<dim3(T_/128, E_*B_), 256, AT_SMEM_>>>(out);
}